// round 16
// baseline (speedup 1.0000x reference)
#include <cuda_runtime.h>
#include <cstdint>

#define N_INPUT   32
#define NTH       512

// Tsit5 tableau
__constant__ float c_C[6] = {0.0f, 0.161f, 0.327f, 0.9f, 0.9800255409045097f, 1.0f};
__constant__ float c_A[5][5] = {
  {0.161f, 0.f, 0.f, 0.f, 0.f},
  {-0.008480655492356989f, 0.335480655492357f, 0.f, 0.f, 0.f},
  {2.8971530571054935f, -6.359448489975075f, 4.3622954328695815f, 0.f, 0.f},
  {5.325864828439257f, -11.748883564062828f, 7.4955393428898365f, -0.09249506636175525f, 0.f},
  {5.86145544294642f, -12.92096931784711f, 8.159367898576159f, -0.071584973281401f, -0.028269050394068383f}
};
__constant__ float c_B[6] = {0.09646076681806523f, 0.01f, 0.4798896504144996f,
                             1.379008574103742f, -3.290069515436081f, 2.324710524099774f};

// ---- smem offsets (bytes) ----
#define OFF_W2S  0        /* full W2 128x256 fp32 = 128 KB            */
#define OFF_W1U  131072   /* W1u local rows: 128x32 fp32 = 16 KB      */
#define OFF_VBUF 147456   /* v double buffer: 2 x 256 fp32 = 2 KB     */
#define OFF_UBUF 149504   /* u staging: 32 fp32                       */
#define OFF_Y0S  149632   /* y0 staging: 128 fp32                     */
#define OFF_B2S  150144   /* b2 staging: 128 fp32                     */
#define OFF_TSH  150656   /* ts cache: 512 fp32                       */
#define OFF_GSH  152704   /* owner-private g history: 5 x 128 fp32    */
#define OFF_MBAR 155264   /* 2 mbarriers                              */
#define SMEM_TOTAL 155392

__device__ __forceinline__ uint32_t smem_u32(const void* p) {
  uint32_t a;
  asm("{ .reg .u64 t; cvta.to.shared.u64 t, %1; cvt.u32.u64 %0, t; }" : "=r"(a) : "l"(p));
  return a;
}
__device__ __forceinline__ uint32_t mapa_peer(uint32_t laddr, uint32_t prank) {
  uint32_t r;
  asm("mapa.shared::cluster.u32 %0, %1, %2;" : "=r"(r) : "r"(laddr), "r"(prank));
  return r;
}
__device__ __forceinline__ void dsmem_st_f32(uint32_t raddr, float v) {
  asm volatile("st.shared::cluster.f32 [%0], %1;" :: "r"(raddr), "f"(v) : "memory");
}
__device__ __forceinline__ void mbar_arrive_remote(uint32_t raddr) {
  asm volatile("mbarrier.arrive.release.cluster.shared::cluster.b64 _, [%0];"
               :: "r"(raddr) : "memory");
}
__device__ __forceinline__ void mbar_wait_cluster(uint32_t addr, uint32_t parity) {
  uint32_t done;
  asm volatile(
    "{\n\t.reg .pred p;\n\t"
    "mbarrier.try_wait.parity.acquire.cluster.shared::cta.b64 p, [%1], %2;\n\t"
    "selp.b32 %0, 1, 0, p;\n\t}"
    : "=r"(done) : "r"(addr), "r"(parity) : "memory");
  while (!done) {
    asm volatile(
      "{\n\t.reg .pred p;\n\t"
      "mbarrier.try_wait.parity.acquire.cluster.shared::cta.b64 p, [%1], %2, 0x989680;\n\t"
      "selp.b32 %0, 1, 0, p;\n\t}"
      : "=r"(done) : "r"(addr), "r"(parity) : "memory");
  }
}
__device__ __forceinline__ float2 ffma2f(float2 a, float2 b, float2 c) {
  union { float2 f; unsigned long long u; } ua, ub, uc;
  ua.f = a; ub.f = b; uc.f = c;
  asm("fma.rn.f32x2 %0, %1, %2, %0;" : "+l"(uc.u) : "l"(ua.u), "l"(ub.u));
  return uc.f;
}
__device__ __forceinline__ float fast_tanh(float x) {
  float ax = fabsf(x);
  float e;
  asm("ex2.approx.f32 %0, %1;" : "=f"(e) : "f"(ax * 2.885390081777927f));
  float r;
  asm("rcp.approx.f32 %0, %1;" : "=f"(r) : "f"(e + 1.0f));
  float t = fmaf(-2.0f, r, 1.0f);
  return copysignf(t, x);
}

__global__ __launch_bounds__(NTH, 1) __cluster_dims__(2, 1, 1)
void ode_tsit5_kernel(const float* __restrict__ ts, const float* __restrict__ y0g,
                      const float* __restrict__ us, const float* __restrict__ W1,
                      const float* __restrict__ b1, const float* __restrict__ W2,
                      const float* __restrict__ b2, float* __restrict__ out,
                      int n_steps)
{
  extern __shared__ char smem[];
  const uint32_t sb = smem_u32(smem);
  const int tid  = threadIdx.x;
  const int lane = tid & 31;
  const int wrp  = tid >> 5;
  uint32_t rank;
  asm("mov.u32 %0, %%cluster_ctarank;" : "=r"(rank));
  const int traj = blockIdx.x >> 1;
  const float* usb = us + (size_t)traj * 512 * N_INPUT;
  float* outb = out + (size_t)traj * 512 * 128;

  const int row     = (wrp << 3) | (lane & 7);   // local preact row 0..127
  const int gr      = 128 * (int)rank + row;     // global hidden row
  const int quarter = lane >> 3;                 // 0..3
  const bool owner  = (quarter == 0);
  const int qb16    = quarter * 16;              // float4 base into v

  float4* w2s4  = (float4*)(smem + OFF_W2S);
  float4* w1u4  = (float4*)(smem + OFF_W1U);
  float*  vbuf  = (float*)(smem + OFF_VBUF);
  float4* vbuf4 = (float4*)(smem + OFF_VBUF);
  float4* ubuf4 = (float4*)(smem + OFF_UBUF);
  float*  ubuff = (float*)(smem + OFF_UBUF);
  float*  y0s   = (float*)(smem + OFF_Y0S);
  float*  b2s   = (float*)(smem + OFF_B2S);
  float*  tsh   = (float*)(smem + OFF_TSH);
  float*  gsh   = (float*)(smem + OFF_GSH);

  // ---- staging ----
  for (int i = tid; i < 8192; i += NTH) w2s4[i] = ((const float4*)W2)[i];
  for (int i = tid; i < 128 * 32; i += NTH) {
    int r = i >> 5, m = i & 31;
    ((float*)w1u4)[i] = W1[(128 * (int)rank + r) * 161 + 129 + m];
  }
  if (tid < 32)  ubuff[tid] = usb[tid];
  if (tid < 128) { y0s[tid] = y0g[traj * 128 + tid]; b2s[tid] = b2[tid]; }
  for (int i = tid; i < n_steps; i += NTH) tsh[i] = ts[i];
  if (tid == 0) {
    asm volatile("mbarrier.init.shared.b64 [%0], %1;" :: "r"(sb + OFF_MBAR),     "r"(128u) : "memory");
    asm volatile("mbarrier.init.shared.b64 [%0], %1;" :: "r"(sb + OFF_MBAR + 8), "r"(128u) : "memory");
  }
  __syncthreads();

  // ---- G init: Greg[j] = G[gr][64*quarter + 4j .. +3], G = W1y @ W2 ----
  float4 Greg[16];
  #pragma unroll
  for (int j = 0; j < 16; ++j) Greg[j] = make_float4(0.f, 0.f, 0.f, 0.f);
  {
    const float* w1row = W1 + gr * 161 + 1;
    for (int m = 0; m < 128; ++m) {
      float w1v = __ldg(w1row + m);
      float2 wv2 = make_float2(w1v, w1v);
      const float4* w2r = w2s4 + m * 64 + qb16;
      #pragma unroll
      for (int j = 0; j < 16; ++j) {
        float4 t = w2r[j];
        float2 lo = ffma2f(wv2, make_float2(t.x, t.y), make_float2(Greg[j].x, Greg[j].y));
        float2 hi = ffma2f(wv2, make_float2(t.z, t.w), make_float2(Greg[j].z, Greg[j].w));
        Greg[j] = make_float4(lo.x, lo.y, hi.x, hi.y);
      }
    }
  }

  // ---- q = W1y@y0, c2 = W1y@b2 (quarter-split dots) ----
  float qreg, c2r;
  {
    float qp = 0.f, cp = 0.f;
    const float* w1row = W1 + gr * 161 + 1 + quarter * 32;
    for (int m = 0; m < 32; ++m) {
      float w1v = __ldg(w1row + m);
      qp = fmaf(w1v, y0s[quarter * 32 + m], qp);
      cp = fmaf(w1v, b2s[quarter * 32 + m], cp);
    }
    qp += __shfl_xor_sync(~0u, qp, 8);  qp += __shfl_xor_sync(~0u, qp, 16);
    cp += __shfl_xor_sync(~0u, cp, 8);  cp += __shfl_xor_sync(~0u, cp, 16);
    qreg = qp; c2r = cp;
  }
  const float wt  = __ldg(W1 + gr * 161);
  const float b1r = __ldg(b1 + gr);

  // ---- U0 = W1u@u_0 (owner) ----
  float U0 = 0.f, HD0 = 0.f, U1 = 0.f, HD1 = 0.f;
  if (owner) {
    float2 a = make_float2(0.f, 0.f);
    #pragma unroll
    for (int j = 0; j < 8; ++j) {
      float4 wv = w1u4[row * 8 + j];
      float4 uv = ubuf4[j];
      a = ffma2f(make_float2(wv.x, wv.y), make_float2(uv.x, uv.y), a);
      a = ffma2f(make_float2(wv.z, wv.w), make_float2(uv.z, uv.w), a);
    }
    U0 = a.x + a.y;
  }

  // ---- y-epilogue roles ----
  const int outl  = 4 * wrp + (lane & 3);   // 0..63
  const int gy    = 64 * (int)rank + outl;  // global state index
  const int slice = lane >> 2;              // 0..7
  float yreg = y0s[gy];
  const float b2y = b2s[gy];
  if (lane < 4) outb[gy] = yreg;            // out row 0 = y0

  const uint32_t prank   = rank ^ 1u;
  const uint32_t peer_vb = mapa_peer(sb + OFF_VBUF, prank);
  const uint32_t peer_mb = mapa_peer(sb + OFF_MBAR, prank);
  __syncthreads();
  asm volatile("barrier.cluster.arrive.aligned;" ::: "memory");
  asm volatile("barrier.cluster.wait.aligned;" ::: "memory");

  unsigned e = 0;   // exchange counter: buffer = e&1, parity = (e>>1)&1

  for (int s = 0; s < n_steps - 1; ++s) {
    const float t0 = tsh[s];
    const float h  = tsh[s + 1] - t0;
    float wacc = 0.f;

    // stage u_{s+1} for the U1 dot (consumed after stage-0's syncthreads)
    if (tid < 8) ubuf4[tid] = ((const float4*)(usb + (size_t)(s + 1) * N_INPUT))[tid];

    // ---- stage 0: v0 = tanh(q + wt*t0 + U0 + b1) ----
    if (owner) {
      float v = fast_tanh(qreg + wt * t0 + U0 + b1r);
      wacc = c_B[0] * v;
      int idx = (e & 1) * 256 + 128 * (int)rank + row;
      vbuf[idx] = v;
      dsmem_st_f32(peer_vb + (uint32_t)idx * 4u, v);
    }
    __syncthreads();
    if (owner) mbar_arrive_remote(peer_mb + (e & 1u) * 8u);
    mbar_wait_cluster(sb + OFF_MBAR + (e & 1u) * 8u, (e >> 1) & 1u);
    int rbuf = e & 1;  ++e;

    if (owner) {   // U1 = W1u@u_{s+1}
      float2 a = make_float2(0.f, 0.f);
      #pragma unroll
      for (int j = 0; j < 8; ++j) {
        float4 wv = w1u4[row * 8 + j];
        float4 uv = ubuf4[j];
        a = ffma2f(make_float2(wv.x, wv.y), make_float2(uv.x, uv.y), a);
        a = ffma2f(make_float2(wv.z, wv.w), make_float2(uv.z, uv.w), a);
      }
      U1 = a.x + a.y;
      HD1 = U1 - U0;
      if (s == 0) HD0 = HD1;
    }

    // ---- stages 1..5: one G-matvec each ----
    #pragma unroll 1
    for (int st = 1; st < 6; ++st) {
      float sum;
      {
        const float4* vb = vbuf4 + rbuf * 64 + qb16;
        float2 a0 = make_float2(0.f, 0.f), a1 = a0;
        #pragma unroll
        for (int j = 0; j < 16; ++j) {
          float4 vv = vb[j];
          float4 gg = Greg[j];
          a0 = ffma2f(make_float2(gg.x, gg.y), make_float2(vv.x, vv.y), a0);
          a1 = ffma2f(make_float2(gg.z, gg.w), make_float2(vv.z, vv.w), a1);
        }
        sum = (a0.x + a0.y) + (a1.x + a1.y);
        sum += __shfl_xor_sync(~0u, sum, 8);
        sum += __shfl_xor_sync(~0u, sum, 16);
      }
      if (owner) {
        float g = sum + c2r;                 // g_{st-1}
        gsh[(st - 1) * 128 + row] = g;       // owner-private (same thread reads)
        float acc = 0.f;
        for (int l = 0; l < st; ++l) acc = fmaf(c_A[st - 1][l], gsh[l * 128 + row], acc);
        float th = c_C[st];
        float t2 = th * th, t3 = t2 * th;
        float up = (2.f*t3 - 3.f*t2 + 1.f) * U0 + (t3 - 2.f*t2 + th) * HD0
                 + (-2.f*t3 + 3.f*t2) * U1 + (t3 - t2) * HD1;
        float pre = qreg + h * acc + wt * fmaf(th, h, t0) + up + b1r;
        float v = fast_tanh(pre);
        wacc = fmaf(c_B[st], v, wacc);
        int idx = (e & 1) * 256 + 128 * (int)rank + row;
        vbuf[idx] = v;
        dsmem_st_f32(peer_vb + (uint32_t)idx * 4u, v);
      }
      __syncthreads();
      if (owner) mbar_arrive_remote(peer_mb + (e & 1u) * 8u);
      mbar_wait_cluster(sb + OFF_MBAR + (e & 1u) * 8u, (e >> 1) & 1u);
      rbuf = e & 1;  ++e;
    }

    // ---- epilogue: exchange w = Σ b_j v_j ----
    if (owner) {
      int idx = (e & 1) * 256 + 128 * (int)rank + row;
      vbuf[idx] = wacc;
      dsmem_st_f32(peer_vb + (uint32_t)idx * 4u, wacc);
    }
    __syncthreads();
    if (owner) mbar_arrive_remote(peer_mb + (e & 1u) * 8u);
    mbar_wait_cluster(sb + OFF_MBAR + (e & 1u) * 8u, (e >> 1) & 1u);
    rbuf = e & 1;  ++e;

    // q += h (G w + c2)
    {
      const float4* vb = vbuf4 + rbuf * 64 + qb16;
      float2 a0 = make_float2(0.f, 0.f), a1 = a0;
      #pragma unroll
      for (int j = 0; j < 16; ++j) {
        float4 vv = vb[j];
        float4 gg = Greg[j];
        a0 = ffma2f(make_float2(gg.x, gg.y), make_float2(vv.x, vv.y), a0);
        a1 = ffma2f(make_float2(gg.z, gg.w), make_float2(vv.z, vv.w), a1);
      }
      float sw = (a0.x + a0.y) + (a1.x + a1.y);
      sw += __shfl_xor_sync(~0u, sw, 8);
      sw += __shfl_xor_sync(~0u, sw, 16);
      if (owner) qreg = fmaf(h, sw + c2r, qreg);
    }
    // y += h (W2 w + b2), write output
    {
      const float4* w2r = w2s4 + gy * 64 + slice * 8;
      const float4* wv  = vbuf4 + rbuf * 64 + slice * 8;
      float2 a0 = make_float2(0.f, 0.f), a1 = a0;
      #pragma unroll
      for (int j = 0; j < 8; ++j) {
        float4 a = w2r[j];
        float4 b = wv[j];
        a0 = ffma2f(make_float2(a.x, a.y), make_float2(b.x, b.y), a0);
        a1 = ffma2f(make_float2(a.z, a.w), make_float2(b.z, b.w), a1);
      }
      float sy = (a0.x + a0.y) + (a1.x + a1.y);
      sy += __shfl_xor_sync(~0u, sy, 4);
      sy += __shfl_xor_sync(~0u, sy, 8);
      sy += __shfl_xor_sync(~0u, sy, 16);
      if (lane < 4) {
        yreg = fmaf(h, sy + b2y, yreg);
        outb[(size_t)(s + 1) * 128 + gy] = yreg;
      }
    }
    // carry U0/HD0 for next step
    if (owner) {
      int s2 = (s + 2 < n_steps) ? s + 2 : n_steps - 1;
      float hn = tsh[s2] - tsh[s + 1];
      HD0 = (hn / h) * HD1;
      U0 = U1;
    }
  }

  asm volatile("barrier.cluster.arrive.aligned;" ::: "memory");
  asm volatile("barrier.cluster.wait.aligned;" ::: "memory");
}

extern "C" void kernel_launch(void* const* d_in, const int* in_sizes, int n_in,
                              void* d_out, int out_size) {
  const float* ts = (const float*)d_in[0];
  const float* y0 = (const float*)d_in[1];
  const float* us = (const float*)d_in[2];
  const float* W1 = (const float*)d_in[3];
  const float* b1 = (const float*)d_in[4];
  const float* W2 = (const float*)d_in[5];
  const float* b2 = (const float*)d_in[6];
  float* out = (float*)d_out;

  const int n_steps = in_sizes[0];             // 512
  const int batch   = in_sizes[1] / 128;       // 64

  cudaFuncSetAttribute(ode_tsit5_kernel,
                       cudaFuncAttributeMaxDynamicSharedMemorySize, SMEM_TOTAL);
  ode_tsit5_kernel<<<batch * 2, NTH, SMEM_TOTAL>>>(ts, y0, us, W1, b1, W2, b2, out, n_steps);
}

// round 17
// speedup vs baseline: 1.3006x; 1.3006x over previous
#include <cuda_runtime.h>
#include <cstdint>

#define N_INPUT   32
#define NTH       256

// Tsit5 tableau
__constant__ float c_C[6] = {0.0f, 0.161f, 0.327f, 0.9f, 0.9800255409045097f, 1.0f};
__constant__ float c_A[5][5] = {
  {0.161f, 0.f, 0.f, 0.f, 0.f},
  {-0.008480655492356989f, 0.335480655492357f, 0.f, 0.f, 0.f},
  {2.8971530571054935f, -6.359448489975075f, 4.3622954328695815f, 0.f, 0.f},
  {5.325864828439257f, -11.748883564062828f, 7.4955393428898365f, -0.09249506636175525f, 0.f},
  {5.86145544294642f, -12.92096931784711f, 8.159367898576159f, -0.071584973281401f, -0.028269050394068383f}
};
__constant__ float c_B[6] = {0.09646076681806523f, 0.01f, 0.4798896504144996f,
                             1.379008574103742f, -3.290069515436081f, 2.324710524099774f};

// ---- smem offsets (bytes) ----
#define OFF_W2S  0        /* full W2 128x256 fp32 = 128 KB            */
#define OFF_W1U  131072   /* W1u local rows: 128x32 fp32 = 16 KB      */
#define OFF_VBUF 147456   /* v double buffer: 2 x 256 fp32 = 2 KB     */
#define OFF_UBUF 149504   /* u staging: 32 fp32                       */
#define OFF_Y0S  149632   /* y0 staging: 128 fp32                     */
#define OFF_B2S  150144   /* b2 staging: 128 fp32                     */
#define OFF_TSH  150656   /* ts cache: 512 fp32                       */
#define OFF_GSH  152704   /* owner-private g history: 5 x 128 fp32    */
#define OFF_MBAR 155264   /* 2 mbarriers                              */
#define SMEM_TOTAL 155392

__device__ __forceinline__ uint32_t smem_u32(const void* p) {
  uint32_t a;
  asm("{ .reg .u64 t; cvta.to.shared.u64 t, %1; cvt.u32.u64 %0, t; }" : "=r"(a) : "l"(p));
  return a;
}
__device__ __forceinline__ uint32_t mapa_peer(uint32_t laddr, uint32_t prank) {
  uint32_t r;
  asm("mapa.shared::cluster.u32 %0, %1, %2;" : "=r"(r) : "r"(laddr), "r"(prank));
  return r;
}
__device__ __forceinline__ void dsmem_st_f32(uint32_t raddr, float v) {
  asm volatile("st.shared::cluster.f32 [%0], %1;" :: "r"(raddr), "f"(v) : "memory");
}
__device__ __forceinline__ void mbar_arrive_remote(uint32_t raddr) {
  asm volatile("mbarrier.arrive.release.cluster.shared::cluster.b64 _, [%0];"
               :: "r"(raddr) : "memory");
}
__device__ __forceinline__ void mbar_wait_cluster(uint32_t addr, uint32_t parity) {
  uint32_t done;
  asm volatile(
    "{\n\t.reg .pred p;\n\t"
    "mbarrier.try_wait.parity.acquire.cluster.shared::cta.b64 p, [%1], %2;\n\t"
    "selp.b32 %0, 1, 0, p;\n\t}"
    : "=r"(done) : "r"(addr), "r"(parity) : "memory");
  while (!done) {
    asm volatile(
      "{\n\t.reg .pred p;\n\t"
      "mbarrier.try_wait.parity.acquire.cluster.shared::cta.b64 p, [%1], %2, 0x989680;\n\t"
      "selp.b32 %0, 1, 0, p;\n\t}"
      : "=r"(done) : "r"(addr), "r"(parity) : "memory");
  }
}
__device__ __forceinline__ float2 ffma2f(float2 a, float2 b, float2 c) {
  union { float2 f; unsigned long long u; } ua, ub, uc;
  ua.f = a; ub.f = b; uc.f = c;
  asm("fma.rn.f32x2 %0, %1, %2, %0;" : "+l"(uc.u) : "l"(ua.u), "l"(ub.u));
  return uc.f;
}
__device__ __forceinline__ float fast_tanh(float x) {
  float ax = fabsf(x);
  float e;
  asm("ex2.approx.f32 %0, %1;" : "=f"(e) : "f"(ax * 2.885390081777927f));
  float r;
  asm("rcp.approx.f32 %0, %1;" : "=f"(r) : "f"(e + 1.0f));
  float t = fmaf(-2.0f, r, 1.0f);
  return copysignf(t, x);
}

__global__ __launch_bounds__(NTH, 1) __cluster_dims__(2, 1, 1)
void ode_tsit5_kernel(const float* __restrict__ ts, const float* __restrict__ y0g,
                      const float* __restrict__ us, const float* __restrict__ W1,
                      const float* __restrict__ b1, const float* __restrict__ W2,
                      const float* __restrict__ b2, float* __restrict__ out,
                      int n_steps)
{
  extern __shared__ char smem[];
  const uint32_t sb = smem_u32(smem);
  const int tid  = threadIdx.x;
  const int lane = tid & 31;
  const int wrp  = tid >> 5;
  uint32_t rank;
  asm("mov.u32 %0, %%cluster_ctarank;" : "=r"(rank));
  const int traj = blockIdx.x >> 1;
  const float* usb = us + (size_t)traj * 512 * N_INPUT;
  float* outb = out + (size_t)traj * 512 * 128;

  // ---- G roles: 2 threads per local G-row (pair = lanes L, L+16) ----
  const int grow  = (wrp << 4) | (lane & 15);  // local row 0..127
  const int gr    = 128 * (int)rank + grow;    // global hidden row
  const int ghalf = lane >> 4;                 // v-column half 0/1
  const bool owner = (ghalf == 0);
  const int gcb   = ghalf * 32;                // float4 col base into v

  // ---- y roles: 4 threads per local output (reduction xor 8, xor 16) ----
  const int yrl   = (wrp << 3) | (lane & 7);   // local out row 0..63
  const int gy    = 64 * (int)rank + yrl;      // global state index
  const int ysl   = lane >> 3;                 // slice 0..3 (64 cols each)

  float4* w2s4  = (float4*)(smem + OFF_W2S);
  float4* w1u4  = (float4*)(smem + OFF_W1U);
  float*  vbuf  = (float*)(smem + OFF_VBUF);
  float4* vbuf4 = (float4*)(smem + OFF_VBUF);
  float4* ubuf4 = (float4*)(smem + OFF_UBUF);
  float*  ubuff = (float*)(smem + OFF_UBUF);
  float*  y0s   = (float*)(smem + OFF_Y0S);
  float*  b2s   = (float*)(smem + OFF_B2S);
  float*  tsh   = (float*)(smem + OFF_TSH);
  float*  gsh   = (float*)(smem + OFF_GSH);

  // ---- staging ----
  for (int i = tid; i < 8192; i += NTH) w2s4[i] = ((const float4*)W2)[i];
  for (int i = tid; i < 128 * 32; i += NTH) {
    int r = i >> 5, m = i & 31;
    ((float*)w1u4)[i] = W1[(128 * (int)rank + r) * 161 + 129 + m];
  }
  if (tid < 32)  ubuff[tid] = usb[tid];
  if (tid < 128) { y0s[tid] = y0g[traj * 128 + tid]; b2s[tid] = b2[tid]; }
  for (int i = tid; i < n_steps; i += NTH) tsh[i] = ts[i];
  if (tid == 0) {
    asm volatile("mbarrier.init.shared.b64 [%0], %1;" :: "r"(sb + OFF_MBAR),     "r"(128u) : "memory");
    asm volatile("mbarrier.init.shared.b64 [%0], %1;" :: "r"(sb + OFF_MBAR + 8), "r"(128u) : "memory");
  }
  __syncthreads();

  // ---- G init: Greg[j] = G[gr][128*ghalf + 4j .. +3], G = W1y @ W2 ----
  float4 Greg[32];
  #pragma unroll
  for (int j = 0; j < 32; ++j) Greg[j] = make_float4(0.f, 0.f, 0.f, 0.f);
  {
    const float* w1row = W1 + gr * 161 + 1;
    for (int m = 0; m < 128; ++m) {
      float w1v = __ldg(w1row + m);
      float2 wv2 = make_float2(w1v, w1v);
      const float4* w2r = w2s4 + m * 64 + gcb;
      #pragma unroll
      for (int j = 0; j < 32; ++j) {
        float4 t = w2r[j];
        float2 lo = ffma2f(wv2, make_float2(t.x, t.y), make_float2(Greg[j].x, Greg[j].y));
        float2 hi = ffma2f(wv2, make_float2(t.z, t.w), make_float2(Greg[j].z, Greg[j].w));
        Greg[j] = make_float4(lo.x, lo.y, hi.x, hi.y);
      }
    }
  }

  // ---- q = W1y@y0, c2 = W1y@b2 (half-split dots, combine xor 16) ----
  float qreg, c2r;
  {
    float qp = 0.f, cp = 0.f;
    const float* w1row = W1 + gr * 161 + 1 + ghalf * 64;
    for (int m = 0; m < 64; ++m) {
      float w1v = __ldg(w1row + m);
      qp = fmaf(w1v, y0s[ghalf * 64 + m], qp);
      cp = fmaf(w1v, b2s[ghalf * 64 + m], cp);
    }
    qp += __shfl_xor_sync(~0u, qp, 16);
    cp += __shfl_xor_sync(~0u, cp, 16);
    qreg = qp; c2r = cp;
  }
  const float wt  = __ldg(W1 + gr * 161);
  const float b1r = __ldg(b1 + gr);

  // ---- U0 = W1u@u_0 (owner-held) ----
  float U0 = 0.f, HD0 = 0.f, U1 = 0.f, HD1 = 0.f;
  if (owner) {
    float2 a = make_float2(0.f, 0.f);
    #pragma unroll
    for (int j = 0; j < 8; ++j) {
      float4 wv = w1u4[grow * 8 + j];
      float4 uv = ubuf4[j];
      a = ffma2f(make_float2(wv.x, wv.y), make_float2(uv.x, uv.y), a);
      a = ffma2f(make_float2(wv.z, wv.w), make_float2(uv.z, uv.w), a);
    }
    U0 = a.x + a.y;
  }

  float yreg = y0s[gy];
  const float b2y = b2s[gy];
  if (ysl == 0) outb[gy] = yreg;            // out row 0 = y0

  const uint32_t prank   = rank ^ 1u;
  const uint32_t peer_vb = mapa_peer(sb + OFF_VBUF, prank);
  const uint32_t peer_mb = mapa_peer(sb + OFF_MBAR, prank);
  __syncthreads();
  asm volatile("barrier.cluster.arrive.aligned;" ::: "memory");
  asm volatile("barrier.cluster.wait.aligned;" ::: "memory");

  unsigned e = 0;   // exchange counter: buffer = e&1, parity = (e>>1)&1

  for (int s = 0; s < n_steps - 1; ++s) {
    const float t0 = tsh[s];
    const float h  = tsh[s + 1] - t0;
    float wacc = 0.f;

    // stage u_{s+1} (consumed after stage-0's syncthreads)
    if (tid < 8) ubuf4[tid] = ((const float4*)(usb + (size_t)(s + 1) * N_INPUT))[tid];

    // ---- stage 0: v0 = tanh(q + wt*t0 + U0 + b1) ----
    if (owner) {
      float v = fast_tanh(qreg + wt * t0 + U0 + b1r);
      wacc = c_B[0] * v;
      int idx = (e & 1) * 256 + 128 * (int)rank + grow;
      vbuf[idx] = v;
      dsmem_st_f32(peer_vb + (uint32_t)idx * 4u, v);
    }
    __syncthreads();
    if (owner) mbar_arrive_remote(peer_mb + (e & 1u) * 8u);
    mbar_wait_cluster(sb + OFF_MBAR + (e & 1u) * 8u, (e >> 1) & 1u);
    int rbuf = e & 1;  ++e;

    if (owner) {   // U1 = W1u@u_{s+1}
      float2 a = make_float2(0.f, 0.f);
      #pragma unroll
      for (int j = 0; j < 8; ++j) {
        float4 wv = w1u4[grow * 8 + j];
        float4 uv = ubuf4[j];
        a = ffma2f(make_float2(wv.x, wv.y), make_float2(uv.x, uv.y), a);
        a = ffma2f(make_float2(wv.z, wv.w), make_float2(uv.z, uv.w), a);
      }
      U1 = a.x + a.y;
      HD1 = U1 - U0;
      if (s == 0) HD0 = HD1;
    }

    // ---- stages 1..5: one G-matvec each (G in registers, v broadcast) ----
    #pragma unroll 1
    for (int st = 1; st < 6; ++st) {
      float sum;
      {
        const float4* vb = vbuf4 + rbuf * 64 + gcb;
        float2 a0 = make_float2(0.f, 0.f), a1 = a0, a2 = a0, a3 = a0;
        #pragma unroll
        for (int j = 0; j < 32; j += 2) {
          float4 vv = vb[j];
          float4 gg = Greg[j];
          a0 = ffma2f(make_float2(gg.x, gg.y), make_float2(vv.x, vv.y), a0);
          a1 = ffma2f(make_float2(gg.z, gg.w), make_float2(vv.z, vv.w), a1);
          float4 vw = vb[j + 1];
          float4 gw = Greg[j + 1];
          a2 = ffma2f(make_float2(gw.x, gw.y), make_float2(vw.x, vw.y), a2);
          a3 = ffma2f(make_float2(gw.z, gw.w), make_float2(vw.z, vw.w), a3);
        }
        sum = ((a0.x + a0.y) + (a1.x + a1.y)) + ((a2.x + a2.y) + (a3.x + a3.y));
        sum += __shfl_xor_sync(~0u, sum, 16);
      }
      if (owner) {
        float g = sum + c2r;                 // g_{st-1}
        gsh[(st - 1) * 128 + grow] = g;      // owner-private (same thread reads)
        float acc = 0.f;
        for (int l = 0; l < st; ++l) acc = fmaf(c_A[st - 1][l], gsh[l * 128 + grow], acc);
        float th = c_C[st];
        float t2 = th * th, t3 = t2 * th;
        float up = (2.f*t3 - 3.f*t2 + 1.f) * U0 + (t3 - 2.f*t2 + th) * HD0
                 + (-2.f*t3 + 3.f*t2) * U1 + (t3 - t2) * HD1;
        float pre = qreg + h * acc + wt * fmaf(th, h, t0) + up + b1r;
        float v = fast_tanh(pre);
        wacc = fmaf(c_B[st], v, wacc);
        int idx = (e & 1) * 256 + 128 * (int)rank + grow;
        vbuf[idx] = v;
        dsmem_st_f32(peer_vb + (uint32_t)idx * 4u, v);
      }
      __syncthreads();
      if (owner) mbar_arrive_remote(peer_mb + (e & 1u) * 8u);
      mbar_wait_cluster(sb + OFF_MBAR + (e & 1u) * 8u, (e >> 1) & 1u);
      rbuf = e & 1;  ++e;
    }

    // ---- epilogue exchange: w = Σ b_j v_j ----
    if (owner) {
      int idx = (e & 1) * 256 + 128 * (int)rank + grow;
      vbuf[idx] = wacc;
      dsmem_st_f32(peer_vb + (uint32_t)idx * 4u, wacc);
    }
    __syncthreads();
    if (owner) mbar_arrive_remote(peer_mb + (e & 1u) * 8u);
    mbar_wait_cluster(sb + OFF_MBAR + (e & 1u) * 8u, (e >> 1) & 1u);
    rbuf = e & 1;  ++e;

    // q += h (G w + c2)
    {
      const float4* vb = vbuf4 + rbuf * 64 + gcb;
      float2 a0 = make_float2(0.f, 0.f), a1 = a0;
      #pragma unroll
      for (int j = 0; j < 32; ++j) {
        float4 vv = vb[j];
        float4 gg = Greg[j];
        a0 = ffma2f(make_float2(gg.x, gg.y), make_float2(vv.x, vv.y), a0);
        a1 = ffma2f(make_float2(gg.z, gg.w), make_float2(vv.z, vv.w), a1);
      }
      float sw = (a0.x + a0.y) + (a1.x + a1.y);
      sw += __shfl_xor_sync(~0u, sw, 16);
      if (owner) qreg = fmaf(h, sw + c2r, qreg);
    }
    // y += h (W2 w + b2), write output (once per step)
    {
      const float4* w2r = w2s4 + gy * 64 + ysl * 16;
      const float4* wv  = vbuf4 + rbuf * 64 + ysl * 16;
      float2 a0 = make_float2(0.f, 0.f), a1 = a0;
      #pragma unroll
      for (int j = 0; j < 16; ++j) {
        float4 a = w2r[j];
        float4 b = wv[j];
        a0 = ffma2f(make_float2(a.x, a.y), make_float2(b.x, b.y), a0);
        a1 = ffma2f(make_float2(a.z, a.w), make_float2(b.z, b.w), a1);
      }
      float sy = (a0.x + a0.y) + (a1.x + a1.y);
      sy += __shfl_xor_sync(~0u, sy, 8);
      sy += __shfl_xor_sync(~0u, sy, 16);
      yreg = fmaf(h, sy + b2y, yreg);
      if (ysl == 0) outb[(size_t)(s + 1) * 128 + gy] = yreg;
    }
    // carry U0/HD0 for next step
    if (owner) {
      int s2 = (s + 2 < n_steps) ? s + 2 : n_steps - 1;
      float hn = tsh[s2] - tsh[s + 1];
      HD0 = (hn / h) * HD1;
      U0 = U1;
    }
  }

  asm volatile("barrier.cluster.arrive.aligned;" ::: "memory");
  asm volatile("barrier.cluster.wait.aligned;" ::: "memory");
}

extern "C" void kernel_launch(void* const* d_in, const int* in_sizes, int n_in,
                              void* d_out, int out_size) {
  const float* ts = (const float*)d_in[0];
  const float* y0 = (const float*)d_in[1];
  const float* us = (const float*)d_in[2];
  const float* W1 = (const float*)d_in[3];
  const float* b1 = (const float*)d_in[4];
  const float* W2 = (const float*)d_in[5];
  const float* b2 = (const float*)d_in[6];
  float* out = (float*)d_out;

  const int n_steps = in_sizes[0];             // 512
  const int batch   = in_sizes[1] / 128;       // 64

  cudaFuncSetAttribute(ode_tsit5_kernel,
                       cudaFuncAttributeMaxDynamicSharedMemorySize, SMEM_TOTAL);
  ode_tsit5_kernel<<<batch * 2, NTH, SMEM_TOTAL>>>(ts, y0, us, W1, b1, W2, b2, out, n_steps);
}